// round 1
// baseline (speedup 1.0000x reference)
#include <cuda_runtime.h>
#include <math.h>

// Problem constants
#define BB   32
#define TT   256     // pred_len / d_model
#define FF   512     // feature dim (mamba seq len)
#define MMK  4       // time-mark feats
#define NV   508     // variates
#define T2K  512
#define ROWS (BB*FF) // 16384

// ---------------- scratch (device globals; no allocation) ----------------
__device__ float g_x    [ROWS*TT];
__device__ float g_xn   [ROWS*TT];
__device__ float g_xp   [ROWS*T2K];
__device__ float g_xc   [ROWS*T2K];
__device__ float g_xco  [ROWS*T2K];
__device__ float g_delta[ROWS*T2K];
__device__ float g_Bm   [ROWS*TT];
__device__ float g_Cm   [ROWS*TT];
__device__ float g_xres [ROWS*T2K];
__device__ float g_gbuf [ROWS*T2K];
__device__ float g_wk   [3*FF*FF];
__device__ float g_mean [BB*NV];
__device__ float g_std  [BB*NV];
__device__ float g_dec  [ROWS*TT];

// ---------------- activations ----------------
__device__ __forceinline__ float siluf(float x) { return x / (1.f + __expf(-x)); }
__device__ __forceinline__ float softplusf(float x) {
    return fmaxf(x, 0.f) + log1pf(__expf(-fabsf(x)));
}

// ---------------- GEMM: C[M,N] (+)= A[M,K] @ B[K,N] (+bias) (act) -------
// 128x128x8 tile, 256 threads, 8x8 per thread (2x2 of 4x4), float4 smem reads.
// bShift shifts the B column index (zero fill out of range) -> conv taps.
// ACT: 0 none, 1 silu, 2 softplus.  BIASMODE: 0 per-col, 1 per-row, 2 none.
template<int ACT, int BIASMODE, bool ACCUM>
__global__ void __launch_bounds__(256) mk_gemm(
    const float* __restrict__ A, long long sA,
    const float* __restrict__ Bmat, long long sB,
    const float* __restrict__ bias,
    float* __restrict__ C, long long sC,
    int Mrows, int K, int Ncols, int bShift)
{
    A    += (long long)blockIdx.z * sA;
    Bmat += (long long)blockIdx.z * sB;
    C    += (long long)blockIdx.z * sC;

    __shared__ __align__(16) float As[8][128];
    __shared__ __align__(16) float Bs[8][128];

    const int tid = threadIdx.x;
    const int m0  = blockIdx.y * 128;
    const int n0  = blockIdx.x * 128;
    const int tx  = tid & 15;      // col group
    const int ty  = tid >> 4;      // row group

    // A tile load: each thread one float4 (row = tid/2, kcol = (tid&1)*4)
    const int arow = tid >> 1;
    const int acol = (tid & 1) * 4;
    // B tile load: each thread 4 scalars (row = tid/32, col = (tid&31)*4)
    const int brow = tid >> 5;
    const int bcol = (tid & 31) * 4;

    float acc[2][2][4][4];
    #pragma unroll
    for (int p = 0; p < 2; p++)
        #pragma unroll
        for (int q = 0; q < 2; q++)
            #pragma unroll
            for (int i = 0; i < 4; i++)
                #pragma unroll
                for (int j = 0; j < 4; j++) acc[p][q][i][j] = 0.f;

    for (int k0 = 0; k0 < K; k0 += 8) {
        float4 av = *(const float4*)(A + (long long)(m0 + arow) * K + k0 + acol);
        As[acol + 0][arow] = av.x;
        As[acol + 1][arow] = av.y;
        As[acol + 2][arow] = av.z;
        As[acol + 3][arow] = av.w;
        #pragma unroll
        for (int j = 0; j < 4; j++) {
            int n = n0 + bcol + j + bShift;
            float v = 0.f;
            if (n >= 0 && n < Ncols)
                v = Bmat[(long long)(k0 + brow) * Ncols + n];
            Bs[brow][bcol + j] = v;
        }
        __syncthreads();

        #pragma unroll
        for (int kk = 0; kk < 8; kk++) {
            float a0[4], a1[4], b0[4], b1[4];
            *(float4*)a0 = *(const float4*)&As[kk][ty * 4];
            *(float4*)a1 = *(const float4*)&As[kk][64 + ty * 4];
            *(float4*)b0 = *(const float4*)&Bs[kk][tx * 4];
            *(float4*)b1 = *(const float4*)&Bs[kk][64 + tx * 4];
            #pragma unroll
            for (int i = 0; i < 4; i++)
                #pragma unroll
                for (int j = 0; j < 4; j++) {
                    acc[0][0][i][j] += a0[i] * b0[j];
                    acc[0][1][i][j] += a0[i] * b1[j];
                    acc[1][0][i][j] += a1[i] * b0[j];
                    acc[1][1][i][j] += a1[i] * b1[j];
                }
        }
        __syncthreads();
    }

    #pragma unroll
    for (int p = 0; p < 2; p++) {
        #pragma unroll
        for (int i = 0; i < 4; i++) {
            int m = m0 + p * 64 + ty * 4 + i;
            #pragma unroll
            for (int q = 0; q < 2; q++) {
                int nbase = n0 + q * 64 + tx * 4;
                float* crow = C + (long long)m * Ncols + nbase;
                #pragma unroll
                for (int j = 0; j < 4; j++) {
                    float c = acc[p][q][i][j];
                    if (ACCUM) c += crow[j];
                    if (BIASMODE == 0) c += bias[nbase + j];
                    if (BIASMODE == 1) c += bias[m];
                    if (ACT == 1) c = siluf(c);
                    if (ACT == 2) c = softplusf(c);
                    crow[j] = c;
                }
            }
        }
    }
}

// ---------------- input normalization + transpose to [B, F, T] ----------
__global__ void mk_norminput(const float* __restrict__ xe, const float* __restrict__ xm,
                             float* __restrict__ x, float* __restrict__ mean,
                             float* __restrict__ stdv)
{
    int idx = blockIdx.x * 256 + threadIdx.x;
    if (idx >= BB * FF) return;
    int f = idx % FF, b = idx / FF;
    float* xr = x + (long long)idx * TT;
    if (f < NV) {
        const float* src = xe + (long long)b * TT * NV + f;
        float s = 0.f, s2 = 0.f;
        for (int t = 0; t < TT; t++) {
            float v = src[(long long)t * NV];
            s += v; s2 += v * v;
        }
        float mu  = s / (float)TT;
        float var = s2 / (float)TT - mu * mu;
        float sd  = sqrtf(var + 1e-5f);
        mean[b * NV + f] = mu;
        stdv[b * NV + f] = sd;
        float inv = 1.f / sd;
        for (int t = 0; t < TT; t++)
            xr[t] = (src[(long long)t * NV] - mu) * inv;
    } else {
        const float* src = xm + (long long)b * TT * MMK + (f - NV);
        for (int t = 0; t < TT; t++)
            xr[t] = src[(long long)t * MMK];
    }
}

// ---------------- rmsnorm over last dim (T=256), one block per row ------
__global__ void mk_rmsnorm(const float* __restrict__ x, const float* __restrict__ w,
                           float* __restrict__ out)
{
    int r = blockIdx.x, t = threadIdx.x;
    __shared__ float red[256];
    float v = x[(long long)r * TT + t];
    red[t] = v * v;
    __syncthreads();
    for (int s = 128; s > 0; s >>= 1) {
        if (t < s) red[t] += red[t + s];
        __syncthreads();
    }
    float scale = rsqrtf(red[0] / (float)TT + 1e-5f);
    out[(long long)r * TT + t] = v * scale * w[t];
}

// ---------------- conv weight tap transpose: W[o][i][k] -> wk[k][o][i] ---
__global__ void mk_convw(const float* __restrict__ W, float* __restrict__ wk)
{
    int idx = blockIdx.x * 256 + threadIdx.x;
    if (idx >= FF * FF * 3) return;
    int k = idx % 3;
    int ii = (idx / 3) % FF;
    int o  = idx / (3 * FF);
    wk[(long long)k * FF * FF + (long long)o * FF + ii] = W[idx];
}

// ---------------- s6 combine: cb = <C,B>; g = silu(delta*x*cb)*xres -----
__global__ void mk_combine(const float* __restrict__ delta, const float* __restrict__ xco,
                           const float* __restrict__ Bm, const float* __restrict__ Cm,
                           const float* __restrict__ xres, float* __restrict__ g)
{
    int r = blockIdx.x, t = threadIdx.x;
    __shared__ float red[256];
    long long rb = (long long)r * TT;
    red[t] = Cm[rb + t] * Bm[rb + t];
    __syncthreads();
    for (int s = 128; s > 0; s >>= 1) {
        if (t < s) red[t] += red[t + s];
        __syncthreads();
    }
    float cb = red[0];
    long long r2 = (long long)r * T2K;
    for (int c = t; c < T2K; c += 256) {
        float xssm = delta[r2 + c] * xco[r2 + c] * cb;
        g[r2 + c] = siluf(xssm) * xres[r2 + c];
    }
}

// ---------------- output: de-normalize + transpose back -----------------
__global__ void mk_output(const float* __restrict__ dec, const float* __restrict__ mean,
                          const float* __restrict__ stdv, float* __restrict__ out)
{
    int idx = blockIdx.x * 256 + threadIdx.x;
    if (idx >= BB * TT * NV) return;
    int n = idx % NV;
    int t = (idx / NV) % TT;
    int b = idx / (NV * TT);
    out[idx] = dec[((long long)b * FF + n) * TT + t] * stdv[b * NV + n] + mean[b * NV + n];
}

// ---------------- host-side launch helpers ------------------------------
template<int ACT, int BIASMODE, bool ACCUM>
static void launch_gemm(const float* A, long long sA, const float* Bmat, long long sB,
                        const float* bias, float* C, long long sC,
                        int M, int K, int N, int shift, int batches)
{
    dim3 grid(N / 128, M / 128, batches);
    mk_gemm<ACT, BIASMODE, ACCUM><<<grid, 256>>>(A, sA, Bmat, sB, bias, C, sC, M, K, N, shift);
}

extern "C" void kernel_launch(void* const* d_in, const int* in_sizes, int n_in,
                              void* d_out, int out_size)
{
    const float* x_enc     = (const float*)d_in[0];
    const float* x_mark    = (const float*)d_in[1];
    const float* norm_w    = (const float*)d_in[4];
    const float* inp_W     = (const float*)d_in[5];
    const float* inp_b     = (const float*)d_in[6];
    const float* conv_W    = (const float*)d_in[7];
    const float* conv_b    = (const float*)d_in[8];
    const float* convlin_W = (const float*)d_in[9];
    const float* convlin_b = (const float*)d_in[10];
    const float* fc1_W     = (const float*)d_in[11];
    const float* fc1_b     = (const float*)d_in[12];
    const float* fc2_W     = (const float*)d_in[13];
    const float* fc2_b     = (const float*)d_in[14];
    const float* fc3_W     = (const float*)d_in[15];
    const float* fc3_b     = (const float*)d_in[16];
    const float* D_W       = (const float*)d_in[17];
    const float* D_b       = (const float*)d_in[18];
    const float* out_W     = (const float*)d_in[19];
    const float* out_b     = (const float*)d_in[20];
    const float* proj_W    = (const float*)d_in[21];
    const float* proj_b    = (const float*)d_in[22];

    float *px, *pxn, *pxp, *pxc, *pxco, *pdelta, *pBm, *pCm, *pxres, *pg, *pwk, *pmean, *pstd, *pdec;
    cudaGetSymbolAddress((void**)&px,    g_x);
    cudaGetSymbolAddress((void**)&pxn,   g_xn);
    cudaGetSymbolAddress((void**)&pxp,   g_xp);
    cudaGetSymbolAddress((void**)&pxc,   g_xc);
    cudaGetSymbolAddress((void**)&pxco,  g_xco);
    cudaGetSymbolAddress((void**)&pdelta,g_delta);
    cudaGetSymbolAddress((void**)&pBm,   g_Bm);
    cudaGetSymbolAddress((void**)&pCm,   g_Cm);
    cudaGetSymbolAddress((void**)&pxres, g_xres);
    cudaGetSymbolAddress((void**)&pg,    g_gbuf);
    cudaGetSymbolAddress((void**)&pwk,   g_wk);
    cudaGetSymbolAddress((void**)&pmean, g_mean);
    cudaGetSymbolAddress((void**)&pstd,  g_std);
    cudaGetSymbolAddress((void**)&pdec,  g_dec);

    const long long sFT2 = (long long)FF * T2K;   // per-batch stride for conv tensors

    mk_norminput<<<(BB * FF + 255) / 256, 256>>>(x_enc, x_mark, px, pmean, pstd);

    for (int i = 0; i < 3; i++) {
        // xn = rmsnorm(x) * w
        mk_rmsnorm<<<ROWS, 256>>>(px, norm_w + i * TT, pxn);
        // xp = xn @ inp_W + inp_b     [ROWS, 512]
        launch_gemm<0, 0, false>(pxn, 0, inp_W + (long long)i * TT * T2K, 0,
                                 inp_b + i * T2K, pxp, 0, ROWS, TT, T2K, 0, 1);
        // conv taps -> contiguous [F,F] matrices
        mk_convw<<<(FF * FF * 3 + 255) / 256, 256>>>(conv_W + (long long)i * FF * FF * 3, pwk);
        // xc = silu(conv1d(xp) + conv_b): 3 shifted batched GEMMs over channels
        launch_gemm<0, 2, false>(pwk + 0LL * FF * FF, 0, pxp, sFT2, nullptr,
                                 pxc, sFT2, FF, FF, T2K, -1, BB);
        launch_gemm<0, 2, true >(pwk + 1LL * FF * FF, 0, pxp, sFT2, nullptr,
                                 pxc, sFT2, FF, FF, T2K,  0, BB);
        launch_gemm<1, 1, true >(pwk + 2LL * FF * FF, 0, pxp, sFT2, conv_b + i * FF,
                                 pxc, sFT2, FF, FF, T2K, +1, BB);
        // xco = xc @ convlin_W + b
        launch_gemm<0, 0, false>(pxc, 0, convlin_W + (long long)i * T2K * T2K, 0,
                                 convlin_b + i * T2K, pxco, 0, ROWS, T2K, T2K, 0, 1);
        // delta = softplus(xco @ fc1_W + b)
        launch_gemm<2, 0, false>(pxco, 0, fc1_W + (long long)i * T2K * T2K, 0,
                                 fc1_b + i * T2K, pdelta, 0, ROWS, T2K, T2K, 0, 1);
        // Bmat / Cmat
        launch_gemm<0, 0, false>(pxco, 0, fc2_W + (long long)i * T2K * TT, 0,
                                 fc2_b + i * TT, pBm, 0, ROWS, T2K, TT, 0, 1);
        launch_gemm<0, 0, false>(pxco, 0, fc3_W + (long long)i * T2K * TT, 0,
                                 fc3_b + i * TT, pCm, 0, ROWS, T2K, TT, 0, 1);
        // xres = silu(xn @ D_W + D_b)
        launch_gemm<1, 0, false>(pxn, 0, D_W + (long long)i * TT * T2K, 0,
                                 D_b + i * T2K, pxres, 0, ROWS, TT, T2K, 0, 1);
        // g = silu(delta * xco * cb) * xres
        mk_combine<<<ROWS, 256>>>(pdelta, pxco, pBm, pCm, pxres, pg);
        // x = g @ out_W + out_b
        launch_gemm<0, 0, false>(pg, 0, out_W + (long long)i * T2K * TT, 0,
                                 out_b + i * TT, px, 0, ROWS, T2K, TT, 0, 1);
    }

    // dec = x @ proj_W + proj_b   [ROWS, 256]
    launch_gemm<0, 0, false>(px, 0, proj_W, 0, proj_b, pdec, 0, ROWS, TT, TT, 0, 1);
    // out[b,t,n] = dec[b,n,t] * std + mean
    mk_output<<<(BB * TT * NV + 255) / 256, 256>>>(pdec, pmean, pstd, (float*)d_out);
}